// round 5
// baseline (speedup 1.0000x reference)
#include <cuda_runtime.h>
#include <cuda_fp16.h>
#include <cuda_bf16.h>

#define BB 256
#define OO 10
#define RR 1152
#define II 8
#define DD 16
#define NITER 3
#define NT 256

// Scratch for priors [B, O, R, D] in fp16 — device global (no allocations).
__device__ __half2 g_priors[(size_t)BB * OO * RR * DD / 2];

// ---- packed f32x2 helpers (Blackwell) --------------------------------------
__device__ __forceinline__ unsigned long long pack2(float a, float b) {
    unsigned long long r;
    asm("mov.b64 %0, {%1, %2};" : "=l"(r) : "f"(a), "f"(b));
    return r;
}
__device__ __forceinline__ unsigned long long fma2(unsigned long long a,
                                                   unsigned long long b,
                                                   unsigned long long c) {
    unsigned long long d;
    asm("fma.rn.f32x2 %0, %1, %2, %3;" : "=l"(d) : "l"(a), "l"(b), "l"(c));
    return d;
}
__device__ __forceinline__ unsigned long long mul2(unsigned long long a,
                                                   unsigned long long b) {
    unsigned long long d;
    asm("mul.rn.f32x2 %0, %1, %2;" : "=l"(d) : "l"(a), "l"(b));
    return d;
}
__device__ __forceinline__ void unpack2(unsigned long long v, float& lo, float& hi) {
    asm("mov.b64 {%0, %1}, %2;" : "=f"(lo), "=f"(hi) : "l"(v));
}

// ---------------------------------------------------------------------------
// Kernel 1: priors[b,o,r,d] = sum_i inputs[b,r,i] * W[o,r,i,d], stored fp16.
// i-paired f32x2; input pairs come free from 128-bit loads.
// Thread owns (o, r, c=4 d's); streams 8 batches, fully unrolled (MLP=16).
// Grid: O(10) * RT(18) * BT(32) = 5760 CTAs x 256 threads.
// ---------------------------------------------------------------------------
__global__ __launch_bounds__(256) void priors_kernel(
    const float* __restrict__ in,   // [B, R, I]
    const float* __restrict__ W,    // [O, R, I, D]
    uint2* __restrict__ out)        // [B, O, R, D] as fp16 (uint2 = 4 halfs)
{
    const int tid = threadIdx.x;
    const int c  = tid & 3;
    const int rl = tid >> 2;                  // 0..63
    const int bt = blockIdx.x & 31;           // 32 b-tiles of 8
    const int rt = (blockIdx.x >> 5) % 18;
    const int o  = (blockIdx.x >> 5) / 18;
    const int r  = rt * 64 + rl;

    // W[o,r,i,4c..4c+3], i=0..7, paired over i.
    const float4* W4 = reinterpret_cast<const float4*>(W);
    const size_t wbase = ((size_t)(o * RR + r) * II) * 4 + c;
    float4 wv[8];
    #pragma unroll
    for (int i = 0; i < 8; ++i) wv[i] = W4[wbase + (size_t)i * 4];

    unsigned long long w2[4][4];
    #pragma unroll
    for (int ip = 0; ip < 4; ++ip) {
        const float* f0 = reinterpret_cast<const float*>(&wv[2 * ip]);
        const float* f1 = reinterpret_cast<const float*>(&wv[2 * ip + 1]);
        #pragma unroll
        for (int dl = 0; dl < 4; ++dl)
            w2[ip][dl] = pack2(f0[dl], f1[dl]);
    }

    const ulonglong2* inp = reinterpret_cast<const ulonglong2*>(in)
                          + ((size_t)(bt * 8) * RR + r) * 2;
    uint2* outp = out + (((size_t)(bt * 8) * OO + o) * RR + r) * 4 + c;

    #pragma unroll
    for (int b = 0; b < 8; ++b) {
        ulonglong2 q0 = inp[(size_t)b * RR * 2];      // (in0,in1),(in2,in3)
        ulonglong2 q1 = inp[(size_t)b * RR * 2 + 1];  // (in4,in5),(in6,in7)

        unsigned long long t0 = mul2(w2[0][0], q0.x);
        unsigned long long t1 = mul2(w2[0][1], q0.x);
        unsigned long long t2 = mul2(w2[0][2], q0.x);
        unsigned long long t3 = mul2(w2[0][3], q0.x);
        t0 = fma2(w2[1][0], q0.y, t0);  t1 = fma2(w2[1][1], q0.y, t1);
        t2 = fma2(w2[1][2], q0.y, t2);  t3 = fma2(w2[1][3], q0.y, t3);
        t0 = fma2(w2[2][0], q1.x, t0);  t1 = fma2(w2[2][1], q1.x, t1);
        t2 = fma2(w2[2][2], q1.x, t2);  t3 = fma2(w2[2][3], q1.x, t3);
        t0 = fma2(w2[3][0], q1.y, t0);  t1 = fma2(w2[3][1], q1.y, t1);
        t2 = fma2(w2[3][2], q1.y, t2);  t3 = fma2(w2[3][3], q1.y, t3);

        float l, h;
        unpack2(t0, l, h); float a0 = l + h;
        unpack2(t1, l, h); float a1 = l + h;
        unpack2(t2, l, h); float a2 = l + h;
        unpack2(t3, l, h); float a3 = l + h;

        __half2 h01 = __floats2half2_rn(a0, a1);
        __half2 h23 = __floats2half2_rn(a2, a3);
        uint2 st;
        st.x = *reinterpret_cast<unsigned*>(&h01);
        st.y = *reinterpret_cast<unsigned*>(&h23);
        outp[(size_t)b * OO * RR * 4] = st;
    }
}

// ---------------------------------------------------------------------------
// Kernel 2: dynamic routing. One CTA per (b,o) (2560 CTAs, 256 threads).
// fp16 tile (36.9 KB) in SMEM. c-pair layout: 2 threads per row, 8 d's each
// (one LDS.128 per row per thread, 1 shuffle per row for the 16-d dot).
// Logits in registers (9/thread). No softmax max-subtraction (logits bounded).
// ---------------------------------------------------------------------------
__global__ __launch_bounds__(NT) void route_kernel(
    const uint4* __restrict__ priG,   // [B, O, R, D] fp16
    float* __restrict__ out)          // [B, O, 1, D] fp32
{
    extern __shared__ float sm[];
    uint4* priH   = reinterpret_cast<uint4*>(sm);    // RR*2 uint4 = 36864 B
    float* wsum   = sm + RR * DD / 2;                // 8 warps * 16
    float* wes    = wsum + 128;                      // 8
    float* svec   = wes + 8;                         // 16
    float* pscale = svec + 16;                       // 1

    const int tid  = threadIdx.x;
    const int lane = tid & 31;
    const int wid  = tid >> 5;
    const int c2   = tid & 1;        // which 8-d half of the row
    const int g2   = tid >> 1;       // 0..127 (row group)
    const int pair = blockIdx.x;     // b * O + o

    // Load fp16 priors tile: 2304 uint4 (row-major, 2 uint4 per row)
    {
        const uint4* gp = priG + (size_t)pair * (RR * DD / 8);
        #pragma unroll
        for (int j = 0; j < 9; ++j)
            priH[j * 256 + tid] = gp[j * 256 + tid];
    }
    __syncthreads();

    float lgr[9];
    #pragma unroll
    for (int j = 0; j < 9; ++j) lgr[j] = 0.0f;
    float scale = 0.0f;
    float sv[8];
    #pragma unroll
    for (int k = 0; k < 8; ++k) sv[k] = 0.0f;

    #pragma unroll
    for (int it = 0; it < NITER; ++it) {
        float acc[8];
        #pragma unroll
        for (int k = 0; k < 8; ++k) acc[k] = 0.0f;
        float es = 0.0f;

        #pragma unroll
        for (int j = 0; j < 9; ++j) {
            uint4 hv = priH[(j * 128 + g2) * 2 + c2];
            float2 f01 = __half22float2(*reinterpret_cast<__half2*>(&hv.x));
            float2 f23 = __half22float2(*reinterpret_cast<__half2*>(&hv.y));
            float2 f45 = __half22float2(*reinterpret_cast<__half2*>(&hv.z));
            float2 f67 = __half22float2(*reinterpret_cast<__half2*>(&hv.w));
            float f[8] = {f01.x, f01.y, f23.x, f23.y,
                          f45.x, f45.y, f67.x, f67.y};
            if (it == 0) {
                #pragma unroll
                for (int k = 0; k < 8; ++k) acc[k] += f[k];
            } else {
                float dt = f[0] * sv[0];
                #pragma unroll
                for (int k = 1; k < 8; ++k) dt += f[k] * sv[k];
                dt += __shfl_xor_sync(0xffffffffu, dt, 1);  // combine halves
                lgr[j] += scale * dt;
                float e = __expf(lgr[j]);
                #pragma unroll
                for (int k = 0; k < 8; ++k) acc[k] += e * f[k];
                es += e;
            }
        }

        // Warp reduce over lanes of same parity (c2 halves stay separate):
        #pragma unroll
        for (int off = 2; off <= 16; off <<= 1) {
            #pragma unroll
            for (int k = 0; k < 8; ++k)
                acc[k] += __shfl_xor_sync(0xffffffffu, acc[k], off);
            es += __shfl_xor_sync(0xffffffffu, es, off);
        }
        if (lane < 2) {  // lane0: d0..7 sums, lane1: d8..15 sums
            float* dst = wsum + wid * 16 + lane * 8;
            #pragma unroll
            for (int k = 0; k < 8; ++k) dst[k] = acc[k];
            if (lane == 0) wes[wid] = es;
        }
        __syncthreads();

        // Finalize svec (16 threads) + squash scale
        if (tid < 16) {
            float s = 0.0f, et = 0.0f;
            #pragma unroll
            for (int w = 0; w < 8; ++w) {
                s  += wsum[w * 16 + tid];
                et += wes[w];
            }
            float svv = (it == 0) ? (s * (1.0f / RR)) : (s / et);
            svec[tid] = svv;
            float sq = svv * svv;
            #pragma unroll
            for (int off = 1; off < 16; off <<= 1)
                sq += __shfl_xor_sync(0x0000ffffu, sq, off);
            if (tid == 0)
                pscale[0] = (sq / (1.0f + sq)) * rsqrtf(sq);
        }
        __syncthreads();
        scale = pscale[0];
        // Thread's 8-d half of svec
        float4 sa = *reinterpret_cast<float4*>(&svec[c2 * 8]);
        float4 sb = *reinterpret_cast<float4*>(&svec[c2 * 8 + 4]);
        sv[0] = sa.x; sv[1] = sa.y; sv[2] = sa.z; sv[3] = sa.w;
        sv[4] = sb.x; sv[5] = sb.y; sv[6] = sb.z; sv[7] = sb.w;
    }

    if (tid < 16)
        out[pair * DD + tid] = scale * svec[tid];
}

// ---------------------------------------------------------------------------
extern "C" void kernel_launch(void* const* d_in, const int* in_sizes, int n_in,
                              void* d_out, int out_size)
{
    const float* in = (const float*)d_in[0];   // inputs [B,R,I]
    const float* W  = (const float*)d_in[1];   // route_weights [O,R,I,D]
    float* out = (float*)d_out;                // [B,O,1,D] fp32

    void* pri = nullptr;
    cudaGetSymbolAddress(&pri, g_priors);

    // K1: 5760 CTAs x 256 threads
    priors_kernel<<<OO * 18 * 32, 256>>>(in, W, (uint2*)pri);

    // K2: 2560 CTAs x 256 threads, ~37.5 KB dynamic SMEM
    const size_t smem = (size_t)(RR * DD / 2 + 128 + 8 + 16 + 8) * sizeof(float);
    cudaFuncSetAttribute(route_kernel,
                         cudaFuncAttributeMaxDynamicSharedMemorySize, (int)smem);
    route_kernel<<<BB * OO, NT, smem>>>((const uint4*)pri, out);
}

// round 6
// speedup vs baseline: 1.1020x; 1.1020x over previous
#include <cuda_runtime.h>
#include <cuda_fp16.h>
#include <cuda_bf16.h>

#define BB 256
#define OO 10
#define RR 1152
#define II 8
#define DD 16
#define NITER 3
#define NT 384

// Scratch for priors [B, O, R, D] in fp16 — device global (no allocations).
__device__ __half2 g_priors[(size_t)BB * OO * RR * DD / 2];

// ---- packed f32x2 helpers (Blackwell) --------------------------------------
__device__ __forceinline__ unsigned long long pack2(float a, float b) {
    unsigned long long r;
    asm("mov.b64 %0, {%1, %2};" : "=l"(r) : "f"(a), "f"(b));
    return r;
}
__device__ __forceinline__ unsigned long long fma2(unsigned long long a,
                                                   unsigned long long b,
                                                   unsigned long long c) {
    unsigned long long d;
    asm("fma.rn.f32x2 %0, %1, %2, %3;" : "=l"(d) : "l"(a), "l"(b), "l"(c));
    return d;
}
__device__ __forceinline__ unsigned long long mul2(unsigned long long a,
                                                   unsigned long long b) {
    unsigned long long d;
    asm("mul.rn.f32x2 %0, %1, %2;" : "=l"(d) : "l"(a), "l"(b));
    return d;
}
__device__ __forceinline__ void unpack2(unsigned long long v, float& lo, float& hi) {
    asm("mov.b64 {%0, %1}, %2;" : "=f"(lo), "=f"(hi) : "l"(v));
}

// ---------------------------------------------------------------------------
// Kernel 1 (reverted to the proven R4 version): priors in fp16.
// i-paired f32x2; input pairs free from 128-bit loads. Thread owns (o,r,c);
// streams 16 batches, unroll 4. Grid: O(10)*RT(18)*BT(16) = 2880 CTAs.
// ---------------------------------------------------------------------------
__global__ __launch_bounds__(256) void priors_kernel(
    const float* __restrict__ in,   // [B, R, I]
    const float* __restrict__ W,    // [O, R, I, D]
    uint2* __restrict__ out)        // [B, O, R, D] as fp16
{
    const int tid = threadIdx.x;
    const int c  = tid & 3;
    const int rl = tid >> 2;                  // 0..63
    const int bt = blockIdx.x & 15;           // 16 b-tiles of 16
    const int rt = (blockIdx.x >> 4) % 18;
    const int o  = (blockIdx.x >> 4) / 18;
    const int r  = rt * 64 + rl;

    const float4* W4 = reinterpret_cast<const float4*>(W);
    const size_t wbase = ((size_t)(o * RR + r) * II) * 4 + c;
    float4 wv[8];
    #pragma unroll
    for (int i = 0; i < 8; ++i) wv[i] = W4[wbase + (size_t)i * 4];

    unsigned long long w2[4][4];
    #pragma unroll
    for (int ip = 0; ip < 4; ++ip) {
        const float* f0 = reinterpret_cast<const float*>(&wv[2 * ip]);
        const float* f1 = reinterpret_cast<const float*>(&wv[2 * ip + 1]);
        #pragma unroll
        for (int dl = 0; dl < 4; ++dl)
            w2[ip][dl] = pack2(f0[dl], f1[dl]);
    }

    const ulonglong2* inp = reinterpret_cast<const ulonglong2*>(in)
                          + ((size_t)(bt * 16) * RR + r) * 2;
    uint2* outp = out + (((size_t)(bt * 16) * OO + o) * RR + r) * 4 + c;

    #pragma unroll 4
    for (int b = 0; b < 16; ++b) {
        ulonglong2 q0 = inp[0];   // (in0,in1),(in2,in3)
        ulonglong2 q1 = inp[1];   // (in4,in5),(in6,in7)

        unsigned long long t0 = mul2(w2[0][0], q0.x);
        unsigned long long t1 = mul2(w2[0][1], q0.x);
        unsigned long long t2 = mul2(w2[0][2], q0.x);
        unsigned long long t3 = mul2(w2[0][3], q0.x);
        t0 = fma2(w2[1][0], q0.y, t0);  t1 = fma2(w2[1][1], q0.y, t1);
        t2 = fma2(w2[1][2], q0.y, t2);  t3 = fma2(w2[1][3], q0.y, t3);
        t0 = fma2(w2[2][0], q1.x, t0);  t1 = fma2(w2[2][1], q1.x, t1);
        t2 = fma2(w2[2][2], q1.x, t2);  t3 = fma2(w2[2][3], q1.x, t3);
        t0 = fma2(w2[3][0], q1.y, t0);  t1 = fma2(w2[3][1], q1.y, t1);
        t2 = fma2(w2[3][2], q1.y, t2);  t3 = fma2(w2[3][3], q1.y, t3);

        float l, h;
        unpack2(t0, l, h); float a0 = l + h;
        unpack2(t1, l, h); float a1 = l + h;
        unpack2(t2, l, h); float a2 = l + h;
        unpack2(t3, l, h); float a3 = l + h;

        __half2 h01 = __floats2half2_rn(a0, a1);
        __half2 h23 = __floats2half2_rn(a2, a3);
        uint2 st;
        st.x = *reinterpret_cast<unsigned*>(&h01);
        st.y = *reinterpret_cast<unsigned*>(&h23);
        *outp = st;

        inp  += RR * 2;
        outp += (size_t)OO * RR * 4;
    }
}

// ---------------------------------------------------------------------------
// Kernel 2: dynamic routing, REGISTER-RESIDENT tile. One CTA per (b,o),
// 384 threads. Thread (g2=tid>>1, c2=tid&1) owns 6 rows x 8-d half in regs
// (6 uint4 = 24 regs). No SMEM tile: zero LDS/STS in the hot passes.
// Logits in regs (6/thread). No softmax max-subtraction (logits bounded).
// ---------------------------------------------------------------------------
__global__ __launch_bounds__(NT, 2) void route_kernel(
    const uint4* __restrict__ priG,   // [B, O, R, D] fp16
    float* __restrict__ out)          // [B, O, 1, D] fp32
{
    __shared__ float wsum[12 * 16];
    __shared__ float wes[12];
    __shared__ float svec[16];
    __shared__ float pscale;

    const int tid  = threadIdx.x;
    const int lane = tid & 31;
    const int wid  = tid >> 5;       // 0..11
    const int c2   = tid & 1;        // which 8-d half of the row
    const int g2   = tid >> 1;       // 0..191 (row group)
    const int pair = blockIdx.x;     // b * O + o

    // Load tile slice straight into registers: rows j*192+g2, half c2.
    uint4 tile[6];
    {
        const uint4* gp = priG + (size_t)pair * (RR * DD / 8);
        #pragma unroll
        for (int j = 0; j < 6; ++j)
            tile[j] = gp[(j * 192 + g2) * 2 + c2];
    }

    float lgr[6];
    #pragma unroll
    for (int j = 0; j < 6; ++j) lgr[j] = 0.0f;
    float scale = 0.0f;
    float sv[8];
    #pragma unroll
    for (int k = 0; k < 8; ++k) sv[k] = 0.0f;

    #pragma unroll
    for (int it = 0; it < NITER; ++it) {
        float acc[8];
        #pragma unroll
        for (int k = 0; k < 8; ++k) acc[k] = 0.0f;
        float es = 0.0f;

        #pragma unroll
        for (int j = 0; j < 6; ++j) {
            float2 f01 = __half22float2(*reinterpret_cast<__half2*>(&tile[j].x));
            float2 f23 = __half22float2(*reinterpret_cast<__half2*>(&tile[j].y));
            float2 f45 = __half22float2(*reinterpret_cast<__half2*>(&tile[j].z));
            float2 f67 = __half22float2(*reinterpret_cast<__half2*>(&tile[j].w));
            float f[8] = {f01.x, f01.y, f23.x, f23.y,
                          f45.x, f45.y, f67.x, f67.y};
            if (it == 0) {
                #pragma unroll
                for (int k = 0; k < 8; ++k) acc[k] += f[k];
            } else {
                float dt = f[0] * sv[0];
                #pragma unroll
                for (int k = 1; k < 8; ++k) dt += f[k] * sv[k];
                dt += __shfl_xor_sync(0xffffffffu, dt, 1);  // join d-halves
                lgr[j] += scale * dt;
                float e = __expf(lgr[j]);
                #pragma unroll
                for (int k = 0; k < 8; ++k) acc[k] += e * f[k];
                es += e;
            }
        }

        // Warp reduce across lanes of same parity (halves stay separate):
        #pragma unroll
        for (int off = 2; off <= 16; off <<= 1) {
            #pragma unroll
            for (int k = 0; k < 8; ++k)
                acc[k] += __shfl_xor_sync(0xffffffffu, acc[k], off);
            es += __shfl_xor_sync(0xffffffffu, es, off);
        }
        if (lane < 2) {  // lane0: d0..7, lane1: d8..15
            float* dst = wsum + wid * 16 + lane * 8;
            #pragma unroll
            for (int k = 0; k < 8; ++k) dst[k] = acc[k];
            if (lane == 0) wes[wid] = es;
        }
        __syncthreads();

        // Finalize svec (16 threads) + squash scale
        if (tid < 16) {
            float s = 0.0f, et = 0.0f;
            #pragma unroll
            for (int w = 0; w < 12; ++w) {
                s  += wsum[w * 16 + tid];
                et += wes[w];
            }
            float svv = (it == 0) ? (s * (1.0f / RR)) : (s / et);
            svec[tid] = svv;
            float sq = svv * svv;
            #pragma unroll
            for (int off = 1; off < 16; off <<= 1)
                sq += __shfl_xor_sync(0x0000ffffu, sq, off);
            if (tid == 0)
                pscale = (sq / (1.0f + sq)) * rsqrtf(sq);
        }
        __syncthreads();
        scale = pscale;
        float4 sa = *reinterpret_cast<float4*>(&svec[c2 * 8]);
        float4 sb = *reinterpret_cast<float4*>(&svec[c2 * 8 + 4]);
        sv[0] = sa.x; sv[1] = sa.y; sv[2] = sa.z; sv[3] = sa.w;
        sv[4] = sb.x; sv[5] = sb.y; sv[6] = sb.z; sv[7] = sb.w;
    }

    if (tid < 16)
        out[pair * DD + tid] = scale * svec[tid];
}

// ---------------------------------------------------------------------------
extern "C" void kernel_launch(void* const* d_in, const int* in_sizes, int n_in,
                              void* d_out, int out_size)
{
    const float* in = (const float*)d_in[0];   // inputs [B,R,I]
    const float* W  = (const float*)d_in[1];   // route_weights [O,R,I,D]
    float* out = (float*)d_out;                // [B,O,1,D] fp32

    void* pri = nullptr;
    cudaGetSymbolAddress(&pri, g_priors);

    // K1: 2880 CTAs x 256 threads (reverted R4 config)
    priors_kernel<<<OO * 18 * 16, 256>>>(in, W, (uint2*)pri);

    // K2: 2560 CTAs x 384 threads, static SMEM only (~1 KB)
    route_kernel<<<BB * OO, NT>>>((const uint4*)pri, out);
}

// round 7
// speedup vs baseline: 1.1640x; 1.0563x over previous
#include <cuda_runtime.h>
#include <cuda_fp16.h>
#include <cuda_bf16.h>

#define BB 256
#define OO 10
#define RR 1152
#define II 8
#define DD 16
#define NITER 3
#define NT 256

// Scratch for priors [B, O, R, D] in fp16 — device global (no allocations).
__device__ __half2 g_priors[(size_t)BB * OO * RR * DD / 2];

// ---- packed f32x2 helpers (Blackwell) --------------------------------------
__device__ __forceinline__ unsigned long long pack2(float a, float b) {
    unsigned long long r;
    asm("mov.b64 %0, {%1, %2};" : "=l"(r) : "f"(a), "f"(b));
    return r;
}
__device__ __forceinline__ unsigned long long fma2(unsigned long long a,
                                                   unsigned long long b,
                                                   unsigned long long c) {
    unsigned long long d;
    asm("fma.rn.f32x2 %0, %1, %2, %3;" : "=l"(d) : "l"(a), "l"(b), "l"(c));
    return d;
}
__device__ __forceinline__ unsigned long long mul2(unsigned long long a,
                                                   unsigned long long b) {
    unsigned long long d;
    asm("mul.rn.f32x2 %0, %1, %2;" : "=l"(d) : "l"(a), "l"(b));
    return d;
}
__device__ __forceinline__ unsigned long long add2(unsigned long long a,
                                                   unsigned long long b) {
    unsigned long long d;
    asm("add.rn.f32x2 %0, %1, %2;" : "=l"(d) : "l"(a), "l"(b));
    return d;
}
__device__ __forceinline__ void unpack2(unsigned long long v, float& lo, float& hi) {
    asm("mov.b64 {%0, %1}, %2;" : "=f"(lo), "=f"(hi) : "l"(v));
}

// ---------------------------------------------------------------------------
// Kernel 1 (R4, proven): priors in fp16. i-paired f32x2; input pairs free
// from 128-bit loads. W read with .cs (read-once) so it does not evict the
// priors being written from L2. Grid: O(10)*RT(18)*BT(16) = 2880 CTAs.
// ---------------------------------------------------------------------------
__global__ __launch_bounds__(256) void priors_kernel(
    const float* __restrict__ in,   // [B, R, I]
    const float* __restrict__ W,    // [O, R, I, D]
    uint2* __restrict__ out)        // [B, O, R, D] as fp16
{
    const int tid = threadIdx.x;
    const int c  = tid & 3;
    const int rl = tid >> 2;                  // 0..63
    const int bt = blockIdx.x & 15;           // 16 b-tiles of 16
    const int rt = (blockIdx.x >> 4) % 18;
    const int o  = (blockIdx.x >> 4) / 18;
    const int r  = rt * 64 + rl;

    const float4* W4 = reinterpret_cast<const float4*>(W);
    const size_t wbase = ((size_t)(o * RR + r) * II) * 4 + c;
    float4 wv[8];
    #pragma unroll
    for (int i = 0; i < 8; ++i) wv[i] = __ldcs(&W4[wbase + (size_t)i * 4]);

    unsigned long long w2[4][4];
    #pragma unroll
    for (int ip = 0; ip < 4; ++ip) {
        const float* f0 = reinterpret_cast<const float*>(&wv[2 * ip]);
        const float* f1 = reinterpret_cast<const float*>(&wv[2 * ip + 1]);
        #pragma unroll
        for (int dl = 0; dl < 4; ++dl)
            w2[ip][dl] = pack2(f0[dl], f1[dl]);
    }

    const ulonglong2* inp = reinterpret_cast<const ulonglong2*>(in)
                          + ((size_t)(bt * 16) * RR + r) * 2;
    uint2* outp = out + (((size_t)(bt * 16) * OO + o) * RR + r) * 4 + c;

    #pragma unroll 4
    for (int b = 0; b < 16; ++b) {
        ulonglong2 q0 = inp[0];   // (in0,in1),(in2,in3)
        ulonglong2 q1 = inp[1];   // (in4,in5),(in6,in7)

        unsigned long long t0 = mul2(w2[0][0], q0.x);
        unsigned long long t1 = mul2(w2[0][1], q0.x);
        unsigned long long t2 = mul2(w2[0][2], q0.x);
        unsigned long long t3 = mul2(w2[0][3], q0.x);
        t0 = fma2(w2[1][0], q0.y, t0);  t1 = fma2(w2[1][1], q0.y, t1);
        t2 = fma2(w2[1][2], q0.y, t2);  t3 = fma2(w2[1][3], q0.y, t3);
        t0 = fma2(w2[2][0], q1.x, t0);  t1 = fma2(w2[2][1], q1.x, t1);
        t2 = fma2(w2[2][2], q1.x, t2);  t3 = fma2(w2[2][3], q1.x, t3);
        t0 = fma2(w2[3][0], q1.y, t0);  t1 = fma2(w2[3][1], q1.y, t1);
        t2 = fma2(w2[3][2], q1.y, t2);  t3 = fma2(w2[3][3], q1.y, t3);

        float l, h;
        unpack2(t0, l, h); float a0 = l + h;
        unpack2(t1, l, h); float a1 = l + h;
        unpack2(t2, l, h); float a2 = l + h;
        unpack2(t3, l, h); float a3 = l + h;

        __half2 h01 = __floats2half2_rn(a0, a1);
        __half2 h23 = __floats2half2_rn(a2, a3);
        uint2 st;
        st.x = *reinterpret_cast<unsigned*>(&h01);
        st.y = *reinterpret_cast<unsigned*>(&h23);
        *outp = st;

        inp  += RR * 2;
        outp += (size_t)OO * RR * 4;
    }
}

// ---------------------------------------------------------------------------
// Kernel 2: dynamic routing (R4 layout + h-trick + f32x2). One CTA per (b,o),
// 256 threads, fp16 tile (36.9 KB) in SMEM, 6 CTAs/SM.
// h-trick: logits are linear in history -> logit_r = u_r . h where
// h = sum_t scale_t*svec_t (one 16-vector in SMEM). No per-row logit state.
// ---------------------------------------------------------------------------
__global__ __launch_bounds__(NT) void route_kernel(
    const uint4* __restrict__ priG,   // [B, O, R, D] fp16
    float* __restrict__ out)          // [B, O, 1, D] fp32
{
    extern __shared__ float sm[];
    uint2* priH   = reinterpret_cast<uint2*>(sm);    // RR*4 uint2 = 36864 B
    float* waccF  = sm + RR * DD / 2;                // 8 warps * 4 c * 4 = 128
    float* wesF   = waccF + 128;                     // 32
    float* svec   = wesF + 32;                       // 16
    float* hvec   = svec + 16;                       // 16 (accumulated h)
    float* pscale = hvec + 16;                       // 1

    const int tid  = threadIdx.x;
    const int lane = tid & 31;
    const int wid  = tid >> 5;
    const int c    = tid & 3;        // d-chunk 0..3
    const int g    = tid >> 2;       // 0..63 (row group)
    const int pair = blockIdx.x;     // b * O + o

    // Load fp16 priors tile: 2304 uint4 (read-once -> .cs)
    {
        const uint4* gp = priG + (size_t)pair * (RR * DD / 8);
        uint4* sp = reinterpret_cast<uint4*>(priH);
        #pragma unroll
        for (int j = 0; j < 9; ++j)
            sp[j * 256 + tid] = __ldcs(&gp[j * 256 + tid]);
    }
    if (tid < 16) hvec[tid] = 0.0f;
    __syncthreads();

    // Packed h for this thread's 4 d's (updated after each finalize)
    unsigned long long h01u = 0, h23u = 0;

    #pragma unroll
    for (int it = 0; it < NITER; ++it) {
        // ---- fused pass: e = exp(u.h), acc += e*u, es += e ----
        unsigned long long acc01 = 0, acc23 = 0;  // packed f32x2 accumulators
        float es = 0.0f;

        #pragma unroll
        for (int j = 0; j < 18; ++j) {
            uint2 hv = priH[(j * 64 + g) * 4 + c];
            float2 f0 = __half22float2(*reinterpret_cast<__half2*>(&hv.x));
            float2 f1 = __half22float2(*reinterpret_cast<__half2*>(&hv.y));
            unsigned long long f01u = pack2(f0.x, f0.y);
            unsigned long long f23u = pack2(f1.x, f1.y);
            if (it == 0) {
                acc01 = add2(acc01, f01u);
                acc23 = add2(acc23, f23u);
            } else {
                unsigned long long d2 = mul2(f01u, h01u);
                d2 = fma2(f23u, h23u, d2);
                float dl, dh;
                unpack2(d2, dl, dh);
                float dt = dl + dh;
                dt += __shfl_xor_sync(0xffffffffu, dt, 1);
                dt += __shfl_xor_sync(0xffffffffu, dt, 2);
                float e = __expf(dt);
                unsigned long long ee = pack2(e, e);
                acc01 = fma2(f01u, ee, acc01);
                acc23 = fma2(f23u, ee, acc23);
                es += e;
            }
        }

        float4 acc;
        unpack2(acc01, acc.x, acc.y);
        unpack2(acc23, acc.z, acc.w);

        // Warp reduce across the 16 row-lanes (c kept separate):
        #pragma unroll
        for (int off = 4; off <= 16; off <<= 1) {
            acc.x += __shfl_xor_sync(0xffffffffu, acc.x, off);
            acc.y += __shfl_xor_sync(0xffffffffu, acc.y, off);
            acc.z += __shfl_xor_sync(0xffffffffu, acc.z, off);
            acc.w += __shfl_xor_sync(0xffffffffu, acc.w, off);
            es    += __shfl_xor_sync(0xffffffffu, es, off);
        }
        if (lane < 4) {
            int i4 = wid * 4 + lane;
            reinterpret_cast<float4*>(waccF)[i4] = acc;
            wesF[i4] = es;
        }
        __syncthreads();

        // ---- finalize svec (16 threads) + squash scale + h update ----
        if (tid < 16) {
            const int c2 = tid >> 2, e2 = tid & 3;
            float s = 0.0f, et = 0.0f;
            #pragma unroll
            for (int w = 0; w < 8; ++w) {
                s  += waccF[(w * 4 + c2) * 4 + e2];
                et += wesF[w * 4 + c2];
            }
            float sv = (it == 0) ? (s * (1.0f / RR)) : (s / et);
            svec[tid] = sv;
            float sq = sv * sv;
            #pragma unroll
            for (int off = 1; off < 16; off <<= 1)
                sq += __shfl_xor_sync(0x0000ffffu, sq, off);
            float sc = (sq / (1.0f + sq)) * rsqrtf(sq);
            if (tid == 0) pscale[0] = sc;
            hvec[tid] += sc * sv;     // h accumulates scale_t * svec_t
        }
        __syncthreads();
        float4 hv4 = reinterpret_cast<float4*>(hvec)[c];
        h01u = pack2(hv4.x, hv4.y);
        h23u = pack2(hv4.z, hv4.w);
    }

    if (tid < 16)
        out[pair * DD + tid] = pscale[0] * svec[tid];
}

// ---------------------------------------------------------------------------
extern "C" void kernel_launch(void* const* d_in, const int* in_sizes, int n_in,
                              void* d_out, int out_size)
{
    const float* in = (const float*)d_in[0];   // inputs [B,R,I]
    const float* W  = (const float*)d_in[1];   // route_weights [O,R,I,D]
    float* out = (float*)d_out;                // [B,O,1,D] fp32

    void* pri = nullptr;
    cudaGetSymbolAddress(&pri, g_priors);

    // K1: 2880 CTAs x 256 threads (R4 config)
    priors_kernel<<<OO * 18 * 16, 256>>>(in, W, (uint2*)pri);

    // K2: 2560 CTAs x 256 threads, ~37.6 KB dynamic SMEM (6 CTAs/SM)
    const size_t smem = (size_t)(RR * DD / 2 + 128 + 32 + 16 + 16 + 8)
                        * sizeof(float);
    cudaFuncSetAttribute(route_kernel,
                         cudaFuncAttributeMaxDynamicSharedMemorySize, (int)smem);
    route_kernel<<<BB * OO, NT, smem>>>((const uint4*)pri, out);
}